// round 16
// baseline (speedup 1.0000x reference)
#include <cuda_runtime.h>
#include <cstdint>

#define B 8
#define H 12
#define S 4096
#define D 64
#define BH (B*H)        // 96
#define TOPK 128
#define QR 64           // q-rows per fused CTA (2 CTAs per head)

// Scratch (device globals; no allocation allowed)
__device__ unsigned g_key[BH * S];       // order-preserving uint importance keys
__device__ int      g_hist[BH * 256];    // per-head top-byte histograms

__device__ __forceinline__ unsigned key_of(float f) {
    unsigned u = __float_as_uint(f);
    return (u & 0x80000000u) ? ~u : (u | 0x80000000u);
}

__device__ __forceinline__ float to_tf32(float x) {
    unsigned u;
    asm("cvt.rna.tf32.f32 %0, %1;" : "=r"(u) : "f"(x));
    return __uint_as_float(u);
}

__device__ __forceinline__ void mma_tf32(float c[4],
                                         unsigned a0, unsigned a1, unsigned a2, unsigned a3,
                                         unsigned b0, unsigned b1) {
    asm volatile(
        "mma.sync.aligned.m16n8k8.row.col.f32.tf32.tf32.f32 "
        "{%0,%1,%2,%3}, {%4,%5,%6,%7}, {%8,%9}, {%0,%1,%2,%3};"
        : "+f"(c[0]), "+f"(c[1]), "+f"(c[2]), "+f"(c[3])
        : "r"(a0), "r"(a1), "r"(a2), "r"(a3), "r"(b0), "r"(b1));
}

// ---------------------------------------------------------------------------
// Kernel 1 (FUSED): importance keys + full-output zero + per-head top-byte
// histogram. Wide grid (3072 CTAs; 32 CTAs per head, 128 rows per CTA).
// ---------------------------------------------------------------------------
__global__ __launch_bounds__(256)
void imp_zero_kernel(const float* __restrict__ q, float* __restrict__ out) {
    __shared__ int hist[256];
    const int tid  = threadIdx.x;
    int warp = (blockIdx.x * blockDim.x + tid) >> 5;
    int lane = tid & 31;
    int sub  = lane >> 3;
    int cl   = lane & 7;
    int r0   = warp * 16 + sub;

    hist[tid] = 0;

    // ---- zero 128 output rows for this block (coalesced STG.128) --------
    {
        float4* obase = reinterpret_cast<float4*>(out) + (size_t)blockIdx.x * 128 * 16;
        const float4 z = make_float4(0.f, 0.f, 0.f, 0.f);
        #pragma unroll
        for (int i = 0; i < 8; i++)
            obase[tid + 256 * i] = z;
    }
    __syncthreads();   // hist zeroed

    // ---- importance keys --------------------------------------------------
    float4 a[4], b[4];
    #pragma unroll
    for (int t = 0; t < 4; t++) {
        const float4* p = reinterpret_cast<const float4*>(q + (size_t)(r0 + 4 * t) * D) + cl;
        a[t] = p[0];
        b[t] = p[8];
    }

    float s[4], s2[4];
    #pragma unroll
    for (int t = 0; t < 4; t++) {
        s[t]  = (a[t].x + a[t].y) + (a[t].z + a[t].w) +
                (b[t].x + b[t].y) + (b[t].z + b[t].w);
        s2[t] = a[t].x * a[t].x + a[t].y * a[t].y + a[t].z * a[t].z + a[t].w * a[t].w +
                b[t].x * b[t].x + b[t].y * b[t].y + b[t].z * b[t].z + b[t].w * b[t].w;
    }
    #pragma unroll
    for (int o = 1; o < 8; o <<= 1)
        #pragma unroll
        for (int t = 0; t < 4; t++) {
            s[t]  += __shfl_xor_sync(0xFFFFFFFFu, s[t],  o);
            s2[t] += __shfl_xor_sync(0xFFFFFFFFu, s2[t], o);
        }

    if (cl == 0) {
        #pragma unroll
        for (int t = 0; t < 4; t++) {
            float mean = s[t] * (1.0f / 64.0f);
            float var  = (s2[t] - s[t] * mean) * (1.0f / 63.0f);
            unsigned key = key_of(mean + sqrtf(fmaxf(var, 0.0f)));
            g_key[r0 + 4 * t] = key;
            atomicAdd(&hist[key >> 24], 1);
        }
    }
    __syncthreads();
    atomicAdd(&g_hist[(blockIdx.x >> 5) * 256 + tid], hist[tid]);
}

// ---------------------------------------------------------------------------
// Kernel 2 (FUSED): top-128 radix select (pass 1 from g_hist; bitmap-collect
// for deterministic sidx ordering) + tf32 attention.
// TWO CTAs per head: 192 CTAs x 512 threads -> 2 CTAs/SM, single wave.
// Both sibling CTAs compute an IDENTICAL ascending-ordered sidx; CTA `half`
// owns q rows sidx[half*64 .. half*64+63].
// ---------------------------------------------------------------------------
#define PITCH  72    // floats per q/k/v row; %32 == 8 -> conflict-free LDS.64
#define PPITCH 136   // floats per ps row;    %32 == 8

__global__ __launch_bounds__(512, 2)
void fused_kernel(const float* __restrict__ q, const float* __restrict__ k,
                  const float* __restrict__ v, float* __restrict__ out) {
    extern __shared__ float sm[];
    unsigned* keys = reinterpret_cast<unsigned*>(sm);   // 16 KB, dead after select
    float* qs = sm;                          // QR  x PITCH (dead after GEMM1)
    float* ks = qs + QR * PITCH;             // 128 x PITCH (dead after GEMM1)
    float* vs = ks + 128 * PITCH;            // 128 x PITCH (unpermuted)
    float* ps = sm;                          // QR  x PPITCH alias over qs+ks

    __shared__ int      sidx[TOPK];
    __shared__ unsigned maskgt[128], maskeq[128];
    __shared__ int      hist[256];
    __shared__ int      wsumg[4], wsume[4];
    __shared__ int      s_digit, s_need;

    const int bh   = blockIdx.x >> 1;
    const int half = blockIdx.x & 1;
    const int tid  = threadIdx.x;
    const int lane = tid & 31;
    const int w    = tid >> 5;           // 16 warps

    // ---- Phase A: radix select; pass 1 precomputed in g_hist --------------
    const unsigned* krow = g_key + (size_t)bh * S;
    for (int i = tid; i < S; i += 512) keys[i] = krow[i];
    if (tid < 256) hist[tid] = g_hist[bh * 256 + tid];
    if (tid < 128) { maskgt[tid] = 0u; maskeq[tid] = 0u; }
    __syncthreads();

    unsigned prefix = 0u;
    int need = TOPK;

    // digit-find for pass 1 (shift=24) on the precomputed hist
    {
        if (tid < 32) {
            int base = 255 - tid * 8;
            int h[8];
            int gs = 0;
            #pragma unroll
            for (int j = 0; j < 8; j++) { h[j] = hist[base - j]; gs += h[j]; }
            int pre = gs;
            #pragma unroll
            for (int o = 1; o < 32; o <<= 1) {
                int t = __shfl_up_sync(0xFFFFFFFFu, pre, o);
                if (tid >= o) pre += t;
            }
            int excl = pre - gs;
            if (excl < need && need <= pre) {
                int cum = excl, j = 0;
                #pragma unroll
                for (; j < 8; j++) { cum += h[j]; if (cum >= need) break; }
                s_digit = base - j;
                s_need  = need - (cum - h[j]);
            }
        }
        __syncthreads();
        prefix = ((unsigned)s_digit) << 24;
        need = s_need;
        __syncthreads();
    }

    // passes 2..4 (shift = 16, 8, 0)
    #pragma unroll
    for (int shift = 16; shift >= 0; shift -= 8) {
        if (tid < 256) hist[tid] = 0;
        __syncthreads();

        unsigned pmask = 0xFFFFFFFFu << (shift + 8);
        for (int i = tid; i < S; i += 512) {
            unsigned u = keys[i];
            if ((u & pmask) == prefix)
                atomicAdd(&hist[(u >> shift) & 255u], 1);
        }
        __syncthreads();

        if (tid < 32) {
            int base = 255 - tid * 8;
            int h[8];
            int gs = 0;
            #pragma unroll
            for (int j = 0; j < 8; j++) { h[j] = hist[base - j]; gs += h[j]; }
            int pre = gs;
            #pragma unroll
            for (int o = 1; o < 32; o <<= 1) {
                int t = __shfl_up_sync(0xFFFFFFFFu, pre, o);
                if (tid >= o) pre += t;
            }
            int excl = pre - gs;
            if (excl < need && need <= pre) {
                int cum = excl, j = 0;
                #pragma unroll
                for (; j < 8; j++) { cum += h[j]; if (cum >= need) break; }
                s_digit = base - j;
                s_need  = need - (cum - h[j]);
            }
        }
        __syncthreads();
        prefix |= ((unsigned)s_digit) << shift;
        need = s_need;
        __syncthreads();
    }

    const unsigned T = prefix;

    // ---- bitmap collect (order-free) + ordered extraction (deterministic)
    for (int i = tid; i < S; i += 512) {
        unsigned u = keys[i];
        if (u > T)       atomicOr(&maskgt[i >> 5], 1u << (i & 31));
        else if (u == T) atomicOr(&maskeq[i >> 5], 1u << (i & 31));
    }
    __syncthreads();

    int cgt = 0, ceq = 0, pg = 0, pe = 0;
    if (tid < 128) {
        cgt = __popc(maskgt[tid]);
        ceq = __popc(maskeq[tid]);
        pg = cgt; pe = ceq;
        #pragma unroll
        for (int o = 1; o < 32; o <<= 1) {
            int tg = __shfl_up_sync(0xFFFFFFFFu, pg, o);
            int te = __shfl_up_sync(0xFFFFFFFFu, pe, o);
            if (lane >= o) { pg += tg; pe += te; }
        }
        if (lane == 31) { wsumg[tid >> 5] = pg; wsume[tid >> 5] = pe; }
    }
    __syncthreads();
    if (tid < 128) {
        int wid4 = tid >> 5;
        int og = 0, oe = 0;
        #pragma unroll
        for (int j = 0; j < 4; j++) {
            if (j < wid4) { og += wsumg[j]; oe += wsume[j]; }
        }
        int exg = og + pg - cgt;                 // exclusive prefix (ascending rows)
        int exe = oe + pe - ceq;
        int G = wsumg[0] + wsumg[1] + wsumg[2] + wsumg[3];   // < TOPK

        unsigned m = maskgt[tid];
        int pos = exg;
        while (m) { int bbit = __ffs(m) - 1; m &= m - 1; sidx[pos++] = tid * 32 + bbit; }
        m = maskeq[tid];
        pos = G + exe;
        while (m && pos < TOPK) { int bbit = __ffs(m) - 1; m &= m - 1; sidx[pos++] = tid * 32 + bbit; }
    }
    __syncthreads();

    const size_t base = (size_t)bh * S * D;

    // ---- Phase B: gather. q (this CTA's 64 rows), k/v (all 128 rows). ----
    {
        const int p8 = tid & 7;
        // q: 8 thr/row x 64 rows = 512 threads exactly
        {
            int r = tid >> 3;
            size_t goff = base + (size_t)sidx[half * QR + r] * D + p8 * 8;
            const float4* gq = reinterpret_cast<const float4*>(q + goff);
            float4 q0 = gq[0], q1 = gq[1];
            q0.x = to_tf32(q0.x); q0.y = to_tf32(q0.y); q0.z = to_tf32(q0.z); q0.w = to_tf32(q0.w);
            q1.x = to_tf32(q1.x); q1.y = to_tf32(q1.y); q1.z = to_tf32(q1.z); q1.w = to_tf32(q1.w);
            float* dq = qs + r * PITCH + p8 * 8;
            reinterpret_cast<float2*>(dq)[0] = make_float2(q0.x, q1.x);
            reinterpret_cast<float2*>(dq)[1] = make_float2(q0.y, q1.y);
            reinterpret_cast<float2*>(dq)[2] = make_float2(q0.z, q1.z);
            reinterpret_cast<float2*>(dq)[3] = make_float2(q0.w, q1.w);
        }
        // k,v: 8 thr/row x 128 rows = 1024 slots -> 2 iterations
        #pragma unroll
        for (int c = 0; c < 2; c++) {
            int r = (tid >> 3) + c * 64;
            size_t goff = base + (size_t)sidx[r] * D + p8 * 8;
            const float4* gk = reinterpret_cast<const float4*>(k + goff);
            const float4* gv = reinterpret_cast<const float4*>(v + goff);
            float4 k0v = gk[0], k1v = gk[1];
            float4 v0 = gv[0], v1 = gv[1];
            k0v.x = to_tf32(k0v.x); k0v.y = to_tf32(k0v.y); k0v.z = to_tf32(k0v.z); k0v.w = to_tf32(k0v.w);
            k1v.x = to_tf32(k1v.x); k1v.y = to_tf32(k1v.y); k1v.z = to_tf32(k1v.z); k1v.w = to_tf32(k1v.w);
            v0.x = to_tf32(v0.x); v0.y = to_tf32(v0.y); v0.z = to_tf32(v0.z); v0.w = to_tf32(v0.w);
            v1.x = to_tf32(v1.x); v1.y = to_tf32(v1.y); v1.z = to_tf32(v1.z); v1.w = to_tf32(v1.w);
            float* dk = ks + r * PITCH + p8 * 8;
            reinterpret_cast<float2*>(dk)[0] = make_float2(k0v.x, k1v.x);
            reinterpret_cast<float2*>(dk)[1] = make_float2(k0v.y, k1v.y);
            reinterpret_cast<float2*>(dk)[2] = make_float2(k0v.z, k1v.z);
            reinterpret_cast<float2*>(dk)[3] = make_float2(k0v.w, k1v.w);
            float* dv = vs + r * PITCH + p8 * 8;
            reinterpret_cast<float4*>(dv)[0] = v0;
            reinterpret_cast<float4*>(dv)[1] = v1;
        }
    }
    __syncthreads();

    const int wm = w & 3;                // 4 m-groups of 16 rows (of this CTA's 64)
    const int wn = w >> 2;               // 4 n-groups
    const int m0 = wm * 16;
    const int lr = lane >> 2;
    const int lc = lane & 3;

    // permuted column indices for ps stores (logical cols 2lc, 2lc+1)
    const int pc0 = (((2 * lc) & 3) << 1) | ((2 * lc) >> 2);
    const int pc1 = (((2 * lc + 1) & 3) << 1) | ((2 * lc + 1) >> 2);

    // ---- Phase C: GEMM1, warp tile 16x32 (4 nb), 8 k-steps, LDS.64 ops ----
    float c1[4][4];
    #pragma unroll
    for (int nb = 0; nb < 4; nb++)
        #pragma unroll
        for (int j = 0; j < 4; j++) c1[nb][j] = 0.0f;

    #pragma unroll
    for (int kk = 0; kk < 8; kk++) {
        const int k0 = kk * 8;
        float2 aA = *reinterpret_cast<const float2*>(&qs[(m0 + lr)     * PITCH + k0 + 2 * lc]);
        float2 aB = *reinterpret_cast<const float2*>(&qs[(m0 + lr + 8) * PITCH + k0 + 2 * lc]);
        unsigned a0 = __float_as_uint(aA.x), a2 = __float_as_uint(aA.y);
        unsigned a1 = __float_as_uint(aB.x), a3 = __float_as_uint(aB.y);
        #pragma unroll
        for (int nb = 0; nb < 4; nb++) {
            const int n0 = wn * 32 + nb * 8;
            float2 bb = *reinterpret_cast<const float2*>(&ks[(n0 + lr) * PITCH + k0 + 2 * lc]);
            mma_tf32(c1[nb], a0, a1, a2, a3,
                     __float_as_uint(bb.x), __float_as_uint(bb.y));
        }
    }
    __syncthreads();   // all warps done reading qs/ks before ps overwrite

    #pragma unroll
    for (int nb = 0; nb < 4; nb++) {
        const int cb = wn * 32 + nb * 8;
        ps[(m0 + lr)     * PPITCH + cb + pc0] = c1[nb][0] * 0.125f;
        ps[(m0 + lr)     * PPITCH + cb + pc1] = c1[nb][1] * 0.125f;
        ps[(m0 + lr + 8) * PPITCH + cb + pc0] = c1[nb][2] * 0.125f;
        ps[(m0 + lr + 8) * PPITCH + cb + pc1] = c1[nb][3] * 0.125f;
    }
    __syncthreads();

    // ---- Phase D: row softmax (16 warps x 4 rows), tf32 probs ------------
    #pragma unroll
    for (int rr = 0; rr < 4; rr++) {
        int r = w * 4 + rr;
        float* row = ps + r * PPITCH;
        float x[4];
        float mx = -1e30f;
        #pragma unroll
        for (int c = 0; c < 4; c++) { x[c] = row[lane + 32 * c]; mx = fmaxf(mx, x[c]); }
        #pragma unroll
        for (int o = 16; o; o >>= 1) mx = fmaxf(mx, __shfl_xor_sync(0xFFFFFFFFu, mx, o));
        float ssum = 0.0f;
        #pragma unroll
        for (int c = 0; c < 4; c++) { x[c] = __expf(x[c] - mx); ssum += x[c]; }
        #pragma unroll
        for (int o = 16; o; o >>= 1) ssum += __shfl_xor_sync(0xFFFFFFFFu, ssum, o);
        float inv = 1.0f / ssum;
        #pragma unroll
        for (int c = 0; c < 4; c++) row[lane + 32 * c] = to_tf32(x[c] * inv);
    }
    __syncthreads();

    // ---- Phase E: GEMM2, warp tile 16x16 (2 nb), 16 k-steps + scatter ----
    float c2[2][4];
    #pragma unroll
    for (int nb = 0; nb < 2; nb++)
        #pragma unroll
        for (int j = 0; j < 4; j++) c2[nb][j] = 0.0f;

    #pragma unroll
    for (int kk = 0; kk < 16; kk++) {
        const int k0 = kk * 8;
        float2 aA = *reinterpret_cast<const float2*>(&ps[(m0 + lr)     * PPITCH + k0 + 2 * lc]);
        float2 aB = *reinterpret_cast<const float2*>(&ps[(m0 + lr + 8) * PPITCH + k0 + 2 * lc]);
        unsigned a0 = __float_as_uint(aA.x), a2 = __float_as_uint(aA.y);
        unsigned a1 = __float_as_uint(aB.x), a3 = __float_as_uint(aB.y);
        #pragma unroll
        for (int nb = 0; nb < 2; nb++) {
            const int n0 = wn * 16 + nb * 8;
            unsigned b0 = __float_as_uint(vs[(k0 + lc)     * PITCH + n0 + lr]);
            unsigned b1 = __float_as_uint(vs[(k0 + lc + 4) * PITCH + n0 + lr]);
            mma_tf32(c2[nb], a0, a1, a2, a3, b0, b1);
        }
    }

    {
        int r0g = sidx[half * QR + m0 + lr];
        int r1g = sidx[half * QR + m0 + lr + 8];
        float* o0 = out + base + (size_t)r0g * D;
        float* o1 = out + base + (size_t)r1g * D;
        #pragma unroll
        for (int nb = 0; nb < 2; nb++) {
            const int d0 = wn * 16 + nb * 8 + lc * 2;
            *reinterpret_cast<float2*>(o0 + d0) = make_float2(c2[nb][0], c2[nb][1]);
            *reinterpret_cast<float2*>(o1 + d0) = make_float2(c2[nb][2], c2[nb][3]);
        }
    }
}

// ---------------------------------------------------------------------------
extern "C" void kernel_launch(void* const* d_in, const int* in_sizes, int n_in,
                              void* d_out, int out_size) {
    const float* q = (const float*)d_in[0];
    const float* k = (const float*)d_in[1];
    const float* v = (const float*)d_in[2];
    float* out = (float*)d_out;

    static void* hist_ptr = nullptr;
    if (hist_ptr == nullptr) cudaGetSymbolAddress(&hist_ptr, g_hist);

    const int fused_smem = ((QR + 2 * 128) * PITCH) * (int)sizeof(float);
    cudaFuncSetAttribute(fused_kernel, cudaFuncAttributeMaxDynamicSharedMemorySize,
                         fused_smem);

    // reset per-head histograms (both sibling CTAs read them -> no self-clean)
    cudaMemsetAsync(hist_ptr, 0, BH * 256 * sizeof(int), 0);

    // 1) importance keys + full output zero + top-byte histograms
    imp_zero_kernel<<<(BH * S) / 128, 256>>>(q, out);

    // 2) fused select + tensor-core attention; 2 CTAs per head, 2 CTAs/SM
    fused_kernel<<<BH * 2, 512, fused_smem>>>(q, k, v, out);
}

// round 17
// speedup vs baseline: 1.0786x; 1.0786x over previous
#include <cuda_runtime.h>
#include <cstdint>

#define B 8
#define H 12
#define S 4096
#define D 64
#define BH (B*H)        // 96
#define TOPK 128

// Scratch (device globals; no allocation allowed)
__device__ unsigned g_key[BH * S];       // order-preserving uint importance keys
__device__ int      g_hist[BH * 256];    // per-head top-byte histograms
                                         // (zero-init at load; fused_kernel
                                         //  self-cleans after reading)

__device__ __forceinline__ unsigned key_of(float f) {
    unsigned u = __float_as_uint(f);
    return (u & 0x80000000u) ? ~u : (u | 0x80000000u);
}

__device__ __forceinline__ float to_tf32(float x) {
    unsigned u;
    asm("cvt.rna.tf32.f32 %0, %1;" : "=r"(u) : "f"(x));
    return __uint_as_float(u);
}

__device__ __forceinline__ void mma_tf32(float c[4],
                                         unsigned a0, unsigned a1, unsigned a2, unsigned a3,
                                         unsigned b0, unsigned b1) {
    asm volatile(
        "mma.sync.aligned.m16n8k8.row.col.f32.tf32.tf32.f32 "
        "{%0,%1,%2,%3}, {%4,%5,%6,%7}, {%8,%9}, {%0,%1,%2,%3};"
        : "+f"(c[0]), "+f"(c[1]), "+f"(c[2]), "+f"(c[3])
        : "r"(a0), "r"(a1), "r"(a2), "r"(a3), "r"(b0), "r"(b1));
}

// ---------------------------------------------------------------------------
// Kernel 1 (FUSED): importance keys + full-output zero + per-head top-byte
// histogram. Wide grid (3072 CTAs; 32 CTAs per head, 128 rows per CTA).
// ---------------------------------------------------------------------------
__global__ __launch_bounds__(256)
void imp_zero_kernel(const float* __restrict__ q, float* __restrict__ out) {
    __shared__ int hist[256];
    const int tid  = threadIdx.x;
    int warp = (blockIdx.x * blockDim.x + tid) >> 5;
    int lane = tid & 31;
    int sub  = lane >> 3;
    int cl   = lane & 7;
    int r0   = warp * 16 + sub;

    hist[tid] = 0;

    // ---- zero 128 output rows for this block (coalesced STG.128) --------
    {
        float4* obase = reinterpret_cast<float4*>(out) + (size_t)blockIdx.x * 128 * 16;
        const float4 z = make_float4(0.f, 0.f, 0.f, 0.f);
        #pragma unroll
        for (int i = 0; i < 8; i++)
            obase[tid + 256 * i] = z;
    }
    __syncthreads();   // hist zeroed

    // ---- importance keys --------------------------------------------------
    float4 a[4], b[4];
    #pragma unroll
    for (int t = 0; t < 4; t++) {
        const float4* p = reinterpret_cast<const float4*>(q + (size_t)(r0 + 4 * t) * D) + cl;
        a[t] = p[0];
        b[t] = p[8];
    }

    float s[4], s2[4];
    #pragma unroll
    for (int t = 0; t < 4; t++) {
        s[t]  = (a[t].x + a[t].y) + (a[t].z + a[t].w) +
                (b[t].x + b[t].y) + (b[t].z + b[t].w);
        s2[t] = a[t].x * a[t].x + a[t].y * a[t].y + a[t].z * a[t].z + a[t].w * a[t].w +
                b[t].x * b[t].x + b[t].y * b[t].y + b[t].z * b[t].z + b[t].w * b[t].w;
    }
    #pragma unroll
    for (int o = 1; o < 8; o <<= 1)
        #pragma unroll
        for (int t = 0; t < 4; t++) {
            s[t]  += __shfl_xor_sync(0xFFFFFFFFu, s[t],  o);
            s2[t] += __shfl_xor_sync(0xFFFFFFFFu, s2[t], o);
        }

    if (cl == 0) {
        #pragma unroll
        for (int t = 0; t < 4; t++) {
            float mean = s[t] * (1.0f / 64.0f);
            float var  = (s2[t] - s[t] * mean) * (1.0f / 63.0f);
            unsigned key = key_of(mean + sqrtf(fmaxf(var, 0.0f)));
            g_key[r0 + 4 * t] = key;
            atomicAdd(&hist[key >> 24], 1);
        }
    }
    __syncthreads();
    atomicAdd(&g_hist[(blockIdx.x >> 5) * 256 + tid], hist[tid]);
}

// ---------------------------------------------------------------------------
// Kernel 2 (FUSED): top-128 radix select (pass 1 from g_hist; keys register-
// resident for passes 2-4 and collect) + tf32 attention.
// One CTA per head: 96 CTAs x 1024 threads.
// ---------------------------------------------------------------------------
#define PITCH  72    // floats per q/k/v row; %32 == 8 -> conflict-free LDS.64
#define PPITCH 136   // floats per ps row;    %32 == 8

__global__ __launch_bounds__(1024, 1)
void fused_kernel(const float* __restrict__ q, const float* __restrict__ k,
                  const float* __restrict__ v, float* __restrict__ out) {
    extern __shared__ float sm[];
    float* qs = sm;                          // 128 x PITCH (dead after GEMM1)
    float* ks = qs + 128 * PITCH;            // 128 x PITCH (dead after GEMM1)
    float* vs = ks + 128 * PITCH;            // 128 x PITCH (unpermuted)
    float* ps = sm;                          // 128 x PPITCH alias over qs+ks

    __shared__ int sidx[TOPK];
    __shared__ int eqidx[TOPK];
    __shared__ int hist[256];
    __shared__ int s_digit, s_need, s_n, s_eq;

    const int bh   = blockIdx.x;
    const int tid  = threadIdx.x;
    const int lane = tid & 31;
    const int w    = tid >> 5;           // 32 warps

    // ---- Phase A: keys into registers; pass 1 precomputed in g_hist -------
    const unsigned* krow = g_key + (size_t)bh * S;
    unsigned kreg[4];
    #pragma unroll
    for (int j = 0; j < 4; j++) kreg[j] = krow[tid + 1024 * j];

    if (tid < 256) {
        hist[tid] = g_hist[bh * 256 + tid];
        g_hist[bh * 256 + tid] = 0;          // self-clean for next replay
    }
    if (tid == 0) { s_n = 0; s_eq = 0; }
    __syncthreads();

    unsigned prefix = 0u;
    int need = TOPK;

    // digit-find for pass 1 (shift=24) on the precomputed hist
    {
        if (tid < 32) {
            int base = 255 - tid * 8;
            int h[8];
            int gs = 0;
            #pragma unroll
            for (int j = 0; j < 8; j++) { h[j] = hist[base - j]; gs += h[j]; }
            int pre = gs;
            #pragma unroll
            for (int o = 1; o < 32; o <<= 1) {
                int t = __shfl_up_sync(0xFFFFFFFFu, pre, o);
                if (tid >= o) pre += t;
            }
            int excl = pre - gs;
            if (excl < need && need <= pre) {
                int cum = excl, j = 0;
                #pragma unroll
                for (; j < 8; j++) { cum += h[j]; if (cum >= need) break; }
                s_digit = base - j;
                s_need  = need - (cum - h[j]);
            }
        }
        __syncthreads();
        prefix = ((unsigned)s_digit) << 24;
        need = s_need;
        __syncthreads();
    }

    // passes 2..4 (shift = 16, 8, 0) over register-resident keys
    #pragma unroll
    for (int shift = 16; shift >= 0; shift -= 8) {
        if (tid < 256) hist[tid] = 0;
        __syncthreads();

        unsigned pmask = 0xFFFFFFFFu << (shift + 8);
        #pragma unroll
        for (int j = 0; j < 4; j++) {
            unsigned u = kreg[j];
            if ((u & pmask) == prefix)
                atomicAdd(&hist[(u >> shift) & 255u], 1);
        }
        __syncthreads();

        if (tid < 32) {
            int base = 255 - tid * 8;
            int h[8];
            int gs = 0;
            #pragma unroll
            for (int j = 0; j < 8; j++) { h[j] = hist[base - j]; gs += h[j]; }
            int pre = gs;
            #pragma unroll
            for (int o = 1; o < 32; o <<= 1) {
                int t = __shfl_up_sync(0xFFFFFFFFu, pre, o);
                if (tid >= o) pre += t;
            }
            int excl = pre - gs;
            if (excl < need && need <= pre) {
                int cum = excl, j = 0;
                #pragma unroll
                for (; j < 8; j++) { cum += h[j]; if (cum >= need) break; }
                s_digit = base - j;
                s_need  = need - (cum - h[j]);
            }
        }
        __syncthreads();
        prefix |= ((unsigned)s_digit) << shift;
        need = s_need;
        __syncthreads();
    }

    const unsigned T = prefix;

    // ---- single collect scan over registers: >T -> sidx, ==T -> capped list
    #pragma unroll
    for (int j = 0; j < 4; j++) {
        unsigned u = kreg[j];
        if (u > T) {
            int p = atomicAdd(&s_n, 1);
            sidx[p] = tid + 1024 * j;
        } else if (u == T) {
            int p = atomicAdd(&s_eq, 1);
            if (p < TOPK) eqidx[p] = tid + 1024 * j;
        }
    }
    __syncthreads();
    {
        int n = s_n;                       // #strictly-greater (< TOPK)
        if (tid < TOPK - n) sidx[n + tid] = eqidx[tid];
    }
    __syncthreads();

    const size_t base = (size_t)bh * S * D;

    // ---- Phase B: gather. q,k stored with permuted-k layout; v plain. ----
    {
        int r = tid >> 3, p8 = tid & 7;            // p8 = which 8-wide k-block
        size_t goff = base + (size_t)sidx[r] * D + p8 * 8;
        const float4* gq = reinterpret_cast<const float4*>(q + goff);
        const float4* gk = reinterpret_cast<const float4*>(k + goff);
        const float4* gv = reinterpret_cast<const float4*>(v + goff);

        float4 q0 = gq[0], q1 = gq[1];
        float4 k0v = gk[0], k1v = gk[1];
        float4 v0 = gv[0], v1 = gv[1];

        q0.x = to_tf32(q0.x); q0.y = to_tf32(q0.y); q0.z = to_tf32(q0.z); q0.w = to_tf32(q0.w);
        q1.x = to_tf32(q1.x); q1.y = to_tf32(q1.y); q1.z = to_tf32(q1.z); q1.w = to_tf32(q1.w);
        k0v.x = to_tf32(k0v.x); k0v.y = to_tf32(k0v.y); k0v.z = to_tf32(k0v.z); k0v.w = to_tf32(k0v.w);
        k1v.x = to_tf32(k1v.x); k1v.y = to_tf32(k1v.y); k1v.z = to_tf32(k1v.z); k1v.w = to_tf32(k1v.w);
        v0.x = to_tf32(v0.x); v0.y = to_tf32(v0.y); v0.z = to_tf32(v0.z); v0.w = to_tf32(v0.w);
        v1.x = to_tf32(v1.x); v1.y = to_tf32(v1.y); v1.z = to_tf32(v1.z); v1.w = to_tf32(v1.w);

        // permuted: physical pair (2i, 2i+1) = logical (k_i, k_{i+4})
        float* dq = qs + r * PITCH + p8 * 8;
        float* dk = ks + r * PITCH + p8 * 8;
        reinterpret_cast<float2*>(dq)[0] = make_float2(q0.x, q1.x);
        reinterpret_cast<float2*>(dq)[1] = make_float2(q0.y, q1.y);
        reinterpret_cast<float2*>(dq)[2] = make_float2(q0.z, q1.z);
        reinterpret_cast<float2*>(dq)[3] = make_float2(q0.w, q1.w);
        reinterpret_cast<float2*>(dk)[0] = make_float2(k0v.x, k1v.x);
        reinterpret_cast<float2*>(dk)[1] = make_float2(k0v.y, k1v.y);
        reinterpret_cast<float2*>(dk)[2] = make_float2(k0v.z, k1v.z);
        reinterpret_cast<float2*>(dk)[3] = make_float2(k0v.w, k1v.w);

        float* dv = vs + r * PITCH + p8 * 8;
        reinterpret_cast<float4*>(dv)[0] = v0;
        reinterpret_cast<float4*>(dv)[1] = v1;
    }
    __syncthreads();

    const int wm = w & 7;                // 8 m-groups of 16 rows
    const int wn = w >> 3;               // 4 n-groups
    const int m0 = wm * 16;
    const int lr = lane >> 2;
    const int lc = lane & 3;

    // permuted column indices for ps stores (logical cols 2lc, 2lc+1)
    const int pc0 = (((2 * lc) & 3) << 1) | ((2 * lc) >> 2);
    const int pc1 = (((2 * lc + 1) & 3) << 1) | ((2 * lc + 1) >> 2);

    // ---- Phase C: GEMM1, warp tile 16x32 (4 nb), 8 k-steps, LDS.64 ops ----
    float c1[4][4];
    #pragma unroll
    for (int nb = 0; nb < 4; nb++)
        #pragma unroll
        for (int j = 0; j < 4; j++) c1[nb][j] = 0.0f;

    #pragma unroll
    for (int kk = 0; kk < 8; kk++) {
        const int k0 = kk * 8;
        float2 aA = *reinterpret_cast<const float2*>(&qs[(m0 + lr)     * PITCH + k0 + 2 * lc]); // (a0,a2)
        float2 aB = *reinterpret_cast<const float2*>(&qs[(m0 + lr + 8) * PITCH + k0 + 2 * lc]); // (a1,a3)
        unsigned a0 = __float_as_uint(aA.x), a2 = __float_as_uint(aA.y);
        unsigned a1 = __float_as_uint(aB.x), a3 = __float_as_uint(aB.y);
        #pragma unroll
        for (int nb = 0; nb < 4; nb++) {
            const int n0 = wn * 32 + nb * 8;
            float2 bb = *reinterpret_cast<const float2*>(&ks[(n0 + lr) * PITCH + k0 + 2 * lc]); // (b0,b1)
            mma_tf32(c1[nb], a0, a1, a2, a3,
                     __float_as_uint(bb.x), __float_as_uint(bb.y));
        }
    }
    __syncthreads();   // all warps done reading qs/ks before ps overwrite

    // store scaled scores at PERMUTED column positions (GEMM2's k layout)
    #pragma unroll
    for (int nb = 0; nb < 4; nb++) {
        const int cb = wn * 32 + nb * 8;   // 8-block base
        ps[(m0 + lr)     * PPITCH + cb + pc0] = c1[nb][0] * 0.125f;
        ps[(m0 + lr)     * PPITCH + cb + pc1] = c1[nb][1] * 0.125f;
        ps[(m0 + lr + 8) * PPITCH + cb + pc0] = c1[nb][2] * 0.125f;
        ps[(m0 + lr + 8) * PPITCH + cb + pc1] = c1[nb][3] * 0.125f;
    }
    __syncthreads();

    // ---- Phase D: row softmax (order-invariant under the permutation) ----
    #pragma unroll
    for (int rr = 0; rr < 4; rr++) {
        int r = w * 4 + rr;
        float* row = ps + r * PPITCH;
        float x[4];
        float mx = -1e30f;
        #pragma unroll
        for (int c = 0; c < 4; c++) { x[c] = row[lane + 32 * c]; mx = fmaxf(mx, x[c]); }
        #pragma unroll
        for (int o = 16; o; o >>= 1) mx = fmaxf(mx, __shfl_xor_sync(0xFFFFFFFFu, mx, o));
        float ssum = 0.0f;
        #pragma unroll
        for (int c = 0; c < 4; c++) { x[c] = __expf(x[c] - mx); ssum += x[c]; }
        #pragma unroll
        for (int o = 16; o; o >>= 1) ssum += __shfl_xor_sync(0xFFFFFFFFu, ssum, o);
        float inv = 1.0f / ssum;
        #pragma unroll
        for (int c = 0; c < 4; c++) row[lane + 32 * c] = to_tf32(x[c] * inv);
    }
    __syncthreads();

    // ---- Phase E: GEMM2, warp tile 16x16 (2 nb), 16 k-steps + scatter ----
    float c2[2][4];
    #pragma unroll
    for (int nb = 0; nb < 2; nb++)
        #pragma unroll
        for (int j = 0; j < 4; j++) c2[nb][j] = 0.0f;

    #pragma unroll
    for (int kk = 0; kk < 16; kk++) {
        const int k0 = kk * 8;
        float2 aA = *reinterpret_cast<const float2*>(&ps[(m0 + lr)     * PPITCH + k0 + 2 * lc]); // (a0,a2)
        float2 aB = *reinterpret_cast<const float2*>(&ps[(m0 + lr + 8) * PPITCH + k0 + 2 * lc]); // (a1,a3)
        unsigned a0 = __float_as_uint(aA.x), a2 = __float_as_uint(aA.y);
        unsigned a1 = __float_as_uint(aB.x), a3 = __float_as_uint(aB.y);
        #pragma unroll
        for (int nb = 0; nb < 2; nb++) {
            const int n0 = wn * 16 + nb * 8;
            unsigned b0 = __float_as_uint(vs[(k0 + lc)     * PITCH + n0 + lr]);
            unsigned b1 = __float_as_uint(vs[(k0 + lc + 4) * PITCH + n0 + lr]);
            mma_tf32(c2[nb], a0, a1, a2, a3, b0, b1);
        }
    }

    {
        int r0g = sidx[m0 + lr];
        int r1g = sidx[m0 + lr + 8];
        float* o0 = out + base + (size_t)r0g * D;
        float* o1 = out + base + (size_t)r1g * D;
        #pragma unroll
        for (int nb = 0; nb < 2; nb++) {
            const int d0 = wn * 16 + nb * 8 + lc * 2;
            *reinterpret_cast<float2*>(o0 + d0) = make_float2(c2[nb][0], c2[nb][1]);
            *reinterpret_cast<float2*>(o1 + d0) = make_float2(c2[nb][2], c2[nb][3]);
        }
    }
}

// ---------------------------------------------------------------------------
extern "C" void kernel_launch(void* const* d_in, const int* in_sizes, int n_in,
                              void* d_out, int out_size) {
    const float* q = (const float*)d_in[0];
    const float* k = (const float*)d_in[1];
    const float* v = (const float*)d_in[2];
    float* out = (float*)d_out;

    const int fused_smem = (3 * 128 * PITCH) * (int)sizeof(float);
    cudaFuncSetAttribute(fused_kernel, cudaFuncAttributeMaxDynamicSharedMemorySize,
                         fused_smem);

    // 1) importance keys + full output zero + top-byte histograms
    //    (g_hist arrives zeroed: static-init on first call, self-cleaned by
    //     fused_kernel on every call thereafter)
    imp_zero_kernel<<<(BH * S) / 128, 256>>>(q, out);

    // 2) fused select + tensor-core attention; overwrites selected rows
    fused_kernel<<<BH, 1024, fused_smem>>>(q, k, v, out);
}